// round 11
// baseline (speedup 1.0000x reference)
#include <cuda_runtime.h>
#include <cuda_fp16.h>
#include <stdint.h>
#include <math.h>

#define B    8
#define C    64
#define T    4096
#define KNN  9
#define ERRB 0.012f   // rigorous fp16 bound: conv 2*2^-11 + 2 chains of 16 adds * 2^-11

typedef unsigned long long u64;
typedef unsigned int       u32;

// Scratch (allocation-free: __device__ globals)
__device__ float g_qT[B * T * C];      // normalized q fp32 [b][t][c]
__device__ float g_kT[B * T * C];      // normalized k fp32
__device__ float g_vT[B * T * C];      // v fp32
__device__ u32   g_qH[B * T * 32];     // half2-packed normalized q
__device__ u32   g_kH[B * T * 32];     // half2-packed normalized k
__device__ float g_wP[KNN * C * C];    // conv_w permuted [kk][cc][o]
__device__ int   g_idx[B * T * KNN];   // top-9 indices per (b,i)

// ---------------------------------------------------------------------------
__device__ __forceinline__ u64 pk2(float lo, float hi) {
    u64 r; asm("mov.b64 %0, {%1, %2};" : "=l"(r) : "f"(lo), "f"(hi)); return r;
}
__device__ __forceinline__ u64 fma2(u64 a, u64 b, u64 c) {
    u64 d; asm("fma.rn.f32x2 %0, %1, %2, %3;" : "=l"(d) : "l"(a), "l"(b), "l"(c));
    return d;
}
__device__ __forceinline__ void unpk(u64 v, float& lo, float& hi) {
    asm("mov.b64 {%0, %1}, %2;" : "=f"(lo), "=f"(hi) : "l"(v));
}
__device__ __forceinline__ __half2 h2(u32 v) {
    return *reinterpret_cast<const __half2*>(&v);
}

// Lex Top9: value desc, index asc on ties (== jax top_k). Any insert order.
struct Top9 {
    float v0,v1,v2,v3,v4,v5,v6,v7,v8;
    int   j0,j1,j2,j3,j4,j5,j6,j7,j8;
    __device__ __forceinline__ void init() {
        v0=v1=v2=v3=v4=v5=v6=v7=v8 = -1.f;
        j0=j1=j2=j3=j4=j5=j6=j7=j8 = 0x7FFFFFFF;
    }
    __device__ __forceinline__ void insert(float s, int j) {
        if ((s > v8) || (s == v8 && j < j8)) {
            v8 = s; j8 = j;
            #define _LSW(va,ja,vb,jb) if (((vb) > (va)) || ((vb) == (va) && (jb) < (ja))) { \
                float tv=(va); (va)=(vb); (vb)=tv; int tj=(ja); (ja)=(jb); (jb)=tj; }
            _LSW(v7,j7,v8,j8); _LSW(v6,j6,v7,j7); _LSW(v5,j5,v6,j6);
            _LSW(v4,j4,v5,j5); _LSW(v3,j3,v4,j4); _LSW(v2,j2,v3,j3);
            _LSW(v1,j1,v2,j2); _LSW(v0,j0,v1,j1);
            #undef _LSW
        }
    }
    __device__ __forceinline__ void store(int* op) {
        op[0]=j0; op[1]=j1; op[2]=j2; op[3]=j3; op[4]=j4;
        op[5]=j5; op[6]=j6; op[7]=j7; op[8]=j8;
    }
};

// exact sequential-chain dot (bitwise reference ranking; validated R3/R8/R10)
__device__ __forceinline__ float exact_dot(const float* kr,
                                           const float* __restrict__ qrow)
{
    float s = 0.f;
    #pragma unroll
    for (int c4 = 0; c4 < 16; c4++) {
        float4 q = __ldg((const float4*)qrow + c4);
        s = __fmaf_rn(kr[4*c4+0], q.x, s);
        s = __fmaf_rn(kr[4*c4+1], q.y, s);
        s = __fmaf_rn(kr[4*c4+2], q.z, s);
        s = __fmaf_rn(kr[4*c4+3], q.w, s);
    }
    return s;
}

#define INS32(key) do { u32 k_ = (key);                                       \
    if (k_ > lst[31]) { lst[31] = k_;                                         \
        _Pragma("unroll")                                                     \
        for (int z_ = 30; z_ >= 0; z_--) {                                    \
            if (lst[z_+1] > lst[z_]) { u32 t_ = lst[z_]; lst[z_] = lst[z_+1]; lst[z_+1] = t_; } \
            else break; } } } while (0)

// ---------------------------------------------------------------------------
__global__ void permute_w_kernel(const float* __restrict__ conv_w) {
    int s = blockIdx.x * 256 + threadIdx.x;
    if (s < KNN * C * C) {
        int o  = s & 63;
        int cc = (s >> 6) & 63;
        int kk = s >> 12;
        g_wP[s] = conv_w[o * (C * KNN) + cc * KNN + kk];
    }
}

// ---------------------------------------------------------------------------
// Kernel 1: projections + L2 normalize; fp32 out + half2 pack
// ---------------------------------------------------------------------------
__global__ __launch_bounds__(128) void proj_kernel(
    const float* __restrict__ x,
    const float* __restrict__ Wq,
    const float* __restrict__ Wk,
    const float* __restrict__ Wv)
{
    __shared__ float Xs[C][128];
    __shared__ float Ws[C][C];

    const int b   = blockIdx.y;
    const int t0  = blockIdx.x * 128;
    const int tid = threadIdx.x;

    const float* xb = x + (size_t)b * C * T;
    for (int c = 0; c < C; c++)
        Xs[c][tid] = xb[c * T + t0 + tid];

    for (int m = 0; m < 3; m++) {
        const float* W = (m == 0) ? Wq : ((m == 1) ? Wk : Wv);
        float* dstbase = (m == 0) ? g_qT : ((m == 1) ? g_kT : g_vT);

        __syncthreads();
        for (int s = tid; s < C * C; s += 128) {
            int c = s >> 6, d = s & 63;
            Ws[c][d] = W[d * C + c];
        }
        __syncthreads();

        float acc[C];
        #pragma unroll
        for (int d = 0; d < C; d++) acc[d] = 0.f;

        for (int c = 0; c < C; c++) {
            float xv = Xs[c][tid];
            const float4* wr = (const float4*)Ws[c];
            #pragma unroll
            for (int d4 = 0; d4 < 16; d4++) {
                float4 w = wr[d4];
                acc[4*d4+0] = __fmaf_rn(w.x, xv, acc[4*d4+0]);
                acc[4*d4+1] = __fmaf_rn(w.y, xv, acc[4*d4+1]);
                acc[4*d4+2] = __fmaf_rn(w.z, xv, acc[4*d4+2]);
                acc[4*d4+3] = __fmaf_rn(w.w, xv, acc[4*d4+3]);
            }
        }

        if (m < 2) {
            float ss = 0.f;
            #pragma unroll
            for (int d = 0; d < C; d++)
                ss = __fadd_rn(ss, __fmul_rn(acc[d], acc[d]));
            float n = fmaxf(sqrtf(ss), 1e-12f);
            #pragma unroll
            for (int d = 0; d < C; d++)
                acc[d] = __fdiv_rn(acc[d], n);
        }

        float4* dst = (float4*)(dstbase + ((size_t)b * T + t0 + tid) * C);
        #pragma unroll
        for (int d4 = 0; d4 < 16; d4++)
            dst[d4] = make_float4(acc[4*d4+0], acc[4*d4+1], acc[4*d4+2], acc[4*d4+3]);

        if (m < 2) {   // half2 pack (round-nearest; rel err <= 2^-11 per value)
            u32 pk[32];
            #pragma unroll
            for (int d2 = 0; d2 < 32; d2++) {
                __half2 h = __floats2half2_rn(acc[2*d2], acc[2*d2+1]);
                pk[d2] = *reinterpret_cast<u32*>(&h);
            }
            u32* dH = ((m == 0) ? g_qH : g_kH) + ((size_t)b * T + t0 + tid) * 32;
            #pragma unroll
            for (int w8 = 0; w8 < 8; w8++)
                *(uint4*)(dH + w8 * 4) = *(uint4*)(pk + w8 * 4);
        }
    }
}

// ---------------------------------------------------------------------------
// Kernel 2: HFMA2 fp16 prefilter (thread-per-row, top-32) -> exact fp32
//           re-rank -> lex Top9; sound per-row bound; warp-coop tier-2.
// ---------------------------------------------------------------------------
__global__ __launch_bounds__(256) void sim_topk_kernel()
{
    __shared__ u32 QHs[256 * 32];    // staged half2 q tile (32 KB)
    __shared__ int t2cnt[8];
    __shared__ int t2lst[8][96];

    const int    b   = blockIdx.y;
    const int    tid = threadIdx.x;
    const int    i   = blockIdx.x * 256 + tid;
    const size_t bT  = (size_t)b * T;

    u32 k2u[32];
    {
        const uint4* kp = (const uint4*)(g_kH + (bT + i) * 32);
        #pragma unroll
        for (int w8 = 0; w8 < 8; w8++) {
            uint4 v = __ldg(kp + w8);
            k2u[w8*4+0] = v.x; k2u[w8*4+1] = v.y;
            k2u[w8*4+2] = v.z; k2u[w8*4+3] = v.w;
        }
    }

    u32 lst[32];
    #pragma unroll
    for (int m = 0; m < 32; m++) lst[m] = 0u;

    const __half2 z2 = __float2half2_rn(0.f);

    for (int jt = 0; jt < T; jt += 256) {
        __syncthreads();
        {
            const uint4* src = (const uint4*)(g_qH + (bT + jt + tid) * 32);
            #pragma unroll
            for (int w8 = 0; w8 < 8; w8++)
                *(uint4*)&QHs[tid * 32 + w8 * 4] = __ldg(src + w8);
        }
        __syncthreads();

        for (int jj = 0; jj < 256; jj += 4) {
            const uint4* qa = (const uint4*)&QHs[(jj + 0) * 32];
            const uint4* qb = (const uint4*)&QHs[(jj + 1) * 32];
            const uint4* qc = (const uint4*)&QHs[(jj + 2) * 32];
            const uint4* qd = (const uint4*)&QHs[(jj + 3) * 32];
            // two 16-add chains per candidate (bounds the fp16 accum error)
            __half2 a0 = z2, a1 = z2, b0 = z2, b1 = z2;
            __half2 c0 = z2, c1 = z2, d0 = z2, d1 = z2;
            #pragma unroll
            for (int t = 0; t < 4; t++) {
                uint4 va = qa[t], vb = qb[t], vc = qc[t], vd = qd[t];
                a0 = __hfma2(h2(k2u[t*4+0]), h2(va.x), a0);
                b0 = __hfma2(h2(k2u[t*4+0]), h2(vb.x), b0);
                c0 = __hfma2(h2(k2u[t*4+0]), h2(vc.x), c0);
                d0 = __hfma2(h2(k2u[t*4+0]), h2(vd.x), d0);
                a0 = __hfma2(h2(k2u[t*4+1]), h2(va.y), a0);
                b0 = __hfma2(h2(k2u[t*4+1]), h2(vb.y), b0);
                c0 = __hfma2(h2(k2u[t*4+1]), h2(vc.y), c0);
                d0 = __hfma2(h2(k2u[t*4+1]), h2(vd.y), d0);
                a0 = __hfma2(h2(k2u[t*4+2]), h2(va.z), a0);
                b0 = __hfma2(h2(k2u[t*4+2]), h2(vb.z), b0);
                c0 = __hfma2(h2(k2u[t*4+2]), h2(vc.z), c0);
                d0 = __hfma2(h2(k2u[t*4+2]), h2(vd.z), d0);
                a0 = __hfma2(h2(k2u[t*4+3]), h2(va.w), a0);
                b0 = __hfma2(h2(k2u[t*4+3]), h2(vb.w), b0);
                c0 = __hfma2(h2(k2u[t*4+3]), h2(vc.w), c0);
                d0 = __hfma2(h2(k2u[t*4+3]), h2(vd.w), d0);
            }
            #pragma unroll
            for (int t = 4; t < 8; t++) {
                uint4 va = qa[t], vb = qb[t], vc = qc[t], vd = qd[t];
                a1 = __hfma2(h2(k2u[t*4+0]), h2(va.x), a1);
                b1 = __hfma2(h2(k2u[t*4+0]), h2(vb.x), b1);
                c1 = __hfma2(h2(k2u[t*4+0]), h2(vc.x), c1);
                d1 = __hfma2(h2(k2u[t*4+0]), h2(vd.x), d1);
                a1 = __hfma2(h2(k2u[t*4+1]), h2(va.y), a1);
                b1 = __hfma2(h2(k2u[t*4+1]), h2(vb.y), b1);
                c1 = __hfma2(h2(k2u[t*4+1]), h2(vc.y), c1);
                d1 = __hfma2(h2(k2u[t*4+1]), h2(vd.y), d1);
                a1 = __hfma2(h2(k2u[t*4+2]), h2(va.z), a1);
                b1 = __hfma2(h2(k2u[t*4+2]), h2(vb.z), b1);
                c1 = __hfma2(h2(k2u[t*4+2]), h2(vc.z), c1);
                d1 = __hfma2(h2(k2u[t*4+2]), h2(vd.z), d1);
                a1 = __hfma2(h2(k2u[t*4+3]), h2(va.w), a1);
                b1 = __hfma2(h2(k2u[t*4+3]), h2(vb.w), b1);
                c1 = __hfma2(h2(k2u[t*4+3]), h2(vc.w), c1);
                d1 = __hfma2(h2(k2u[t*4+3]), h2(vd.w), d1);
            }
            float sa = (__low2float(a0) + __high2float(a0)) +
                       (__low2float(a1) + __high2float(a1));
            float sb = (__low2float(b0) + __high2float(b0)) +
                       (__low2float(b1) + __high2float(b1));
            float sc = (__low2float(c0) + __high2float(c0)) +
                       (__low2float(c1) + __high2float(c1));
            float sd = (__low2float(d0) + __high2float(d0)) +
                       (__low2float(d1) + __high2float(d1));
            sa = fmaxf(sa, 0.f); sb = fmaxf(sb, 0.f);
            sc = fmaxf(sc, 0.f); sd = fmaxf(sd, 0.f);
            u32 ka = (__float_as_uint(sa) & 0xFFFFF000u) | (u32)(4095 - (jt + jj));
            u32 kb = (__float_as_uint(sb) & 0xFFFFF000u) | (u32)(4095 - (jt + jj + 1));
            u32 kc = (__float_as_uint(sc) & 0xFFFFF000u) | (u32)(4095 - (jt + jj + 2));
            u32 kd = (__float_as_uint(sd) & 0xFFFFF000u) | (u32)(4095 - (jt + jj + 3));
            INS32(ka); INS32(kb); INS32(kc); INS32(kd);
        }
    }

    // exact fp32 k row
    float kr[C];
    {
        const float4* kp4 = (const float4*)(g_kT + (bT + i) * C);
        #pragma unroll
        for (int c4 = 0; c4 < 16; c4++) {
            float4 v = __ldg(kp4 + c4);
            kr[4*c4+0] = v.x; kr[4*c4+1] = v.y; kr[4*c4+2] = v.z; kr[4*c4+3] = v.w;
        }
    }

    Top9 t9;
    t9.init();
    #pragma unroll
    for (int m = 0; m < 32; m++) {
        int j = 4095 - (int)(lst[m] & 0xFFFu);
        float s = exact_dot(kr, g_qT + (bT + j) * C);
        t9.insert(fmaxf(s, 0.f), j);
    }
    float v9c = t9.v8;

    // sound coverage: excluded j have approx <= bucket-upper(cut), exact <= that + ERRB
    float cutU = __uint_as_float((((lst[31] >> 12) + 2u) << 12));
    int   flag = (cutU + ERRB >= v9c) ? 1 : 0;

    // ---- tier-2: warp-cooperative threshold re-sweep for flagged rows ----
    const unsigned fm = 0xffffffffu;
    const int w = tid >> 5, lane = tid & 31;
    unsigned bal = __ballot_sync(fm, flag);
    while (bal) {
        int r = __ffs(bal) - 1;
        bal &= bal - 1;
        u32 kb2[32];
        #pragma unroll
        for (int t = 0; t < 32; t++) kb2[t] = __shfl_sync(fm, k2u[t], r);
        float theta = __shfl_sync(fm, v9c, r) - ERRB;
        if (lane == 0) t2cnt[w] = 0;
        __syncwarp();
        for (int j = lane; j < T; j += 32) {
            const uint4* qp = (const uint4*)(g_qH + (bT + j) * 32);
            __half2 s0 = z2, s1 = z2;
            #pragma unroll
            for (int t = 0; t < 4; t++) {
                uint4 v = __ldg(qp + t);
                s0 = __hfma2(h2(kb2[t*4+0]), h2(v.x), s0);
                s0 = __hfma2(h2(kb2[t*4+1]), h2(v.y), s0);
                s0 = __hfma2(h2(kb2[t*4+2]), h2(v.z), s0);
                s0 = __hfma2(h2(kb2[t*4+3]), h2(v.w), s0);
            }
            #pragma unroll
            for (int t = 4; t < 8; t++) {
                uint4 v = __ldg(qp + t);
                s1 = __hfma2(h2(kb2[t*4+0]), h2(v.x), s1);
                s1 = __hfma2(h2(kb2[t*4+1]), h2(v.y), s1);
                s1 = __hfma2(h2(kb2[t*4+2]), h2(v.z), s1);
                s1 = __hfma2(h2(kb2[t*4+3]), h2(v.w), s1);
            }
            float sh = (__low2float(s0) + __high2float(s0)) +
                       (__low2float(s1) + __high2float(s1));
            sh = fmaxf(sh, 0.f);
            if (sh >= theta) {
                int p = atomicAdd(&t2cnt[w], 1);
                if (p < 96) t2lst[w][p] = j;
            }
        }
        __syncwarp();
        if (lane == r) {
            int n = t2cnt[w];
            t9.init();
            if (n > 96) {   // ultimate fallback: full exact scan
                for (int j = 0; j < T; j++) {
                    float s = exact_dot(kr, g_qT + (bT + j) * C);
                    t9.insert(fmaxf(s, 0.f), j);
                }
            } else {
                for (int e = 0; e < n; e++) {
                    int j = t2lst[w][e];
                    float s = exact_dot(kr, g_qT + (bT + j) * C);
                    t9.insert(fmaxf(s, 0.f), j);
                }
            }
        }
        __syncwarp();
    }

    t9.store(g_idx + (bT + i) * KNN);
}

// ---------------------------------------------------------------------------
// Kernel 3: gather v + 1x1 conv (576 -> 64) + bias (R4 version, 92us)
// ---------------------------------------------------------------------------
__global__ __launch_bounds__(128) void gather_conv_kernel(
    const float* __restrict__ conv_b,
    float* __restrict__ out)
{
    __shared__ float  Ws[C * C];
    __shared__ float4 Vs[4][16][33];

    const int b   = blockIdx.y;
    const int tid = threadIdx.x;
    const int w   = tid >> 5;
    const int l   = tid & 31;
    const int i   = blockIdx.x * 128 + tid;

    u64 accp[32];
    #pragma unroll
    for (int o2 = 0; o2 < 32; o2++) accp[o2] = 0ull;

    const int base = (b * T + i) * KNN;

    for (int kk = 0; kk < KNN; kk++) {
        __syncthreads();
        {
            const float4* wsrc = (const float4*)(g_wP + kk * C * C);
            float4* wdst = (float4*)Ws;
            #pragma unroll
            for (int r = 0; r < 8; r++)
                wdst[r * 128 + tid] = wsrc[r * 128 + tid];
        }

        int j = g_idx[base + kk];

        #pragma unroll
        for (int rp = 0; rp < 32; rp += 2) {
            int r  = rp + (l >> 4);
            int c4 = l & 15;
            int jr = __shfl_sync(0xffffffffu, j, r);
            float4 vv = ((const float4*)(g_vT + ((size_t)b * T + jr) * C))[c4];
            Vs[w][c4][r] = vv;
        }
        __syncthreads();

        #pragma unroll
        for (int c4 = 0; c4 < 16; c4++) {
            float4 xv = Vs[w][c4][l];
            float xs[4] = {xv.x, xv.y, xv.z, xv.w};
            #pragma unroll
            for (int e = 0; e < 4; e++) {
                u64 xd = pk2(xs[e], xs[e]);
                const ulonglong2* wr = (const ulonglong2*)(Ws + (c4 * 4 + e) * C);
                #pragma unroll
                for (int o4 = 0; o4 < 16; o4++) {
                    ulonglong2 wp = wr[o4];
                    accp[2*o4+0] = fma2(xd, wp.x, accp[2*o4+0]);
                    accp[2*o4+1] = fma2(xd, wp.y, accp[2*o4+1]);
                }
            }
        }
    }

    #pragma unroll
    for (int o2 = 0; o2 < 32; o2++) {
        float f0, f1;
        unpk(accp[o2], f0, f1);
        out[((size_t)(b * C + 2*o2 + 0)) * T + i] = f0 + __ldg(&conv_b[2*o2 + 0]);
        out[((size_t)(b * C + 2*o2 + 1)) * T + i] = f1 + __ldg(&conv_b[2*o2 + 1]);
    }
}

// ---------------------------------------------------------------------------
extern "C" void kernel_launch(void* const* d_in, const int* in_sizes, int n_in,
                              void* d_out, int out_size)
{
    const float* x      = (const float*)d_in[0];
    const float* Wq     = (const float*)d_in[1];
    const float* Wk     = (const float*)d_in[2];
    const float* Wv     = (const float*)d_in[3];
    const float* conv_w = (const float*)d_in[4];
    const float* conv_b = (const float*)d_in[5];
    float* out          = (float*)d_out;

    permute_w_kernel<<<(KNN * C * C + 255) / 256, 256>>>(conv_w);
    proj_kernel<<<dim3(T / 128, B), 128>>>(x, Wq, Wk, Wv);
    sim_topk_kernel<<<dim3(T / 256, B), 256>>>();
    gather_conv_kernel<<<dim3(T / 128, B), 128>>>(conv_b, out);
}

// round 12
// speedup vs baseline: 8.5438x; 8.5438x over previous
#include <cuda_runtime.h>
#include <stdint.h>
#include <math.h>

#define B    8
#define C    64
#define T    4096
#define KNN  9

typedef unsigned long long u64;
typedef unsigned int       u32;

// Scratch (allocation-free: __device__ globals)
__device__ float g_qT[B * T * C];      // normalized q fp32 [b][t][c]
__device__ float g_kT[B * T * C];      // normalized k fp32
__device__ float g_vT[B * T * C];      // v fp32
__device__ float g_wP[KNN * C * C];    // conv_w permuted [kk][cc][o]
__device__ int   g_idx[B * T * KNN];   // top-9 indices per (b,i)

// ---------------------------------------------------------------------------
__device__ __forceinline__ u64 pk2(float lo, float hi) {
    u64 r; asm("mov.b64 %0, {%1, %2};" : "=l"(r) : "f"(lo), "f"(hi)); return r;
}
__device__ __forceinline__ u64 fma2(u64 a, u64 b, u64 c) {
    u64 d; asm("fma.rn.f32x2 %0, %1, %2, %3;" : "=l"(d) : "l"(a), "l"(b), "l"(c));
    return d;
}
__device__ __forceinline__ void unpk(u64 v, float& lo, float& hi) {
    asm("mov.b64 {%0, %1}, %2;" : "=f"(lo), "=f"(hi) : "l"(v));
}

// ---------------------------------------------------------------------------
__global__ void permute_w_kernel(const float* __restrict__ conv_w) {
    int s = blockIdx.x * 256 + threadIdx.x;
    if (s < KNN * C * C) {
        int o  = s & 63;
        int cc = (s >> 6) & 63;
        int kk = s >> 12;
        g_wP[s] = conv_w[o * (C * KNN) + cc * KNN + kk];
    }
}

// ---------------------------------------------------------------------------
// Kernel 1: projections + L2 normalize (q,k); fp32 outputs.
// Numerics validated at rel_err 5.3e-7 (R3).
// ---------------------------------------------------------------------------
__global__ __launch_bounds__(128) void proj_kernel(
    const float* __restrict__ x,
    const float* __restrict__ Wq,
    const float* __restrict__ Wk,
    const float* __restrict__ Wv)
{
    __shared__ float Xs[C][128];
    __shared__ float Ws[C][C];

    const int b   = blockIdx.y;
    const int t0  = blockIdx.x * 128;
    const int tid = threadIdx.x;

    const float* xb = x + (size_t)b * C * T;
    for (int c = 0; c < C; c++)
        Xs[c][tid] = xb[c * T + t0 + tid];

    for (int m = 0; m < 3; m++) {
        const float* W = (m == 0) ? Wq : ((m == 1) ? Wk : Wv);
        float* dstbase = (m == 0) ? g_qT : ((m == 1) ? g_kT : g_vT);

        __syncthreads();
        for (int s = tid; s < C * C; s += 128) {
            int c = s >> 6, d = s & 63;
            Ws[c][d] = W[d * C + c];
        }
        __syncthreads();

        float acc[C];
        #pragma unroll
        for (int d = 0; d < C; d++) acc[d] = 0.f;

        for (int c = 0; c < C; c++) {
            float xv = Xs[c][tid];
            const float4* wr = (const float4*)Ws[c];
            #pragma unroll
            for (int d4 = 0; d4 < 16; d4++) {
                float4 w = wr[d4];
                acc[4*d4+0] = __fmaf_rn(w.x, xv, acc[4*d4+0]);
                acc[4*d4+1] = __fmaf_rn(w.y, xv, acc[4*d4+1]);
                acc[4*d4+2] = __fmaf_rn(w.z, xv, acc[4*d4+2]);
                acc[4*d4+3] = __fmaf_rn(w.w, xv, acc[4*d4+3]);
            }
        }

        if (m < 2) {
            float ss = 0.f;
            #pragma unroll
            for (int d = 0; d < C; d++)
                ss = __fadd_rn(ss, __fmul_rn(acc[d], acc[d]));
            float n = fmaxf(sqrtf(ss), 1e-12f);
            #pragma unroll
            for (int d = 0; d < C; d++)
                acc[d] = __fdiv_rn(acc[d], n);
        }

        float4* dst = (float4*)(dstbase + ((size_t)b * T + t0 + tid) * C);
        #pragma unroll
        for (int d4 = 0; d4 < 16; d4++)
            dst[d4] = make_float4(acc[4*d4+0], acc[4*d4+1], acc[4*d4+2], acc[4*d4+3]);
    }
}

// ---------------------------------------------------------------------------
// Kernel 2: exact fp32 sim + streaming top-9.
// 8 interleaved sequential FMA chains; double-buffered 64-row q tiles with
// register prefetch; one __syncthreads per tile.
// ---------------------------------------------------------------------------
#define CSWAP(va, ja, vb, jb)                                     \
    do { if ((vb) > (va)) {                                       \
        float _tv = (va); (va) = (vb); (vb) = _tv;                \
        int   _tj = (ja); (ja) = (jb); (jb) = _tj; } } while (0)

#define TOPK_INSERT(s, j)                                         \
    do { if ((s) > v8) {                                          \
        v8 = (s); j8 = (j);                                       \
        CSWAP(v7, j7, v8, j8);                                    \
        CSWAP(v6, j6, v7, j7);                                    \
        CSWAP(v5, j5, v6, j6);                                    \
        CSWAP(v4, j4, v5, j5);                                    \
        CSWAP(v3, j3, v4, j4);                                    \
        CSWAP(v2, j2, v3, j3);                                    \
        CSWAP(v1, j1, v2, j2);                                    \
        CSWAP(v0, j0, v1, j1); } } while (0)

#define CHAIN4(s, kq, v)                                          \
    s = __fmaf_rn((kq)[0], (v).x, s);                             \
    s = __fmaf_rn((kq)[1], (v).y, s);                             \
    s = __fmaf_rn((kq)[2], (v).z, s);                             \
    s = __fmaf_rn((kq)[3], (v).w, s)

__global__ __launch_bounds__(256) void sim_topk_kernel()
{
    __shared__ __align__(16) float Qs[2][64 * C];   // 2 x 16 KB

    const int    b   = blockIdx.y;
    const int    tid = threadIdx.x;
    const int    i   = blockIdx.x * 256 + tid;
    const size_t bT  = (size_t)b * T;

    float kr[C];
    {
        const float4* kp = (const float4*)(g_kT + (bT + i) * C);
        #pragma unroll
        for (int c4 = 0; c4 < 16; c4++) {
            float4 v = __ldg(kp + c4);
            kr[4*c4+0] = v.x; kr[4*c4+1] = v.y;
            kr[4*c4+2] = v.z; kr[4*c4+3] = v.w;
        }
    }

    float v0=-1.f,v1=-1.f,v2=-1.f,v3=-1.f,v4=-1.f,v5=-1.f,v6=-1.f,v7=-1.f,v8=-1.f;
    int   j0=0,j1=0,j2=0,j3=0,j4=0,j5=0,j6=0,j7=0,j8=0;

    // per-thread staging coords: 4 float4 per thread per tile
    int r0 = (tid * 4 + 0) >> 4, c0 = (tid * 4 + 0) & 15;
    int r1 = (tid * 4 + 1) >> 4, c1 = (tid * 4 + 1) & 15;
    int r2 = (tid * 4 + 2) >> 4, c2 = (tid * 4 + 2) & 15;
    int r3 = (tid * 4 + 3) >> 4, c3 = (tid * 4 + 3) & 15;
    const float* s0p = g_qT + (bT + r0) * C + c0 * 4;
    const float* s1p = g_qT + (bT + r1) * C + c1 * 4;
    const float* s2p = g_qT + (bT + r2) * C + c2 * 4;
    const float* s3p = g_qT + (bT + r3) * C + c3 * 4;

    // stage tile 0
    {
        float4* dst = (float4*)Qs[0];
        dst[tid*4+0] = __ldg((const float4*)s0p);
        dst[tid*4+1] = __ldg((const float4*)s1p);
        dst[tid*4+2] = __ldg((const float4*)s2p);
        dst[tid*4+3] = __ldg((const float4*)s3p);
    }
    __syncthreads();

    for (int t = 0; t < T / 64; t++) {
        const float* Q = Qs[t & 1];

        // prefetch next tile into registers (hidden under compute)
        float4 pf0, pf1, pf2, pf3;
        if (t + 1 < T / 64) {
            const float* nb = (const float*)0;
            (void)nb;
            size_t adv = (size_t)(t + 1) * 64 * C;
            pf0 = __ldg((const float4*)(s0p + adv));
            pf1 = __ldg((const float4*)(s1p + adv));
            pf2 = __ldg((const float4*)(s2p + adv));
            pf3 = __ldg((const float4*)(s3p + adv));
        }

        for (int g = 0; g < 8; g++) {
            const float4* qb = (const float4*)(Q + g * 8 * C);
            // 8 strictly-sequential chains (exact reference dot order)
            float sa=0.f,sb=0.f,sc=0.f,sd=0.f,se=0.f,sf=0.f,sg=0.f,sh=0.f;
            #pragma unroll
            for (int c4 = 0; c4 < 16; c4++) {
                const float* kq = kr + c4 * 4;
                float4 a = qb[c4 +   0], bq = qb[c4 +  16];
                float4 cq = qb[c4 + 32], dq = qb[c4 +  48];
                CHAIN4(sa, kq, a);  CHAIN4(sb, kq, bq);
                CHAIN4(sc, kq, cq); CHAIN4(sd, kq, dq);
                float4 e = qb[c4 + 64], fq = qb[c4 +  80];
                float4 gq = qb[c4 + 96], hq = qb[c4 + 112];
                CHAIN4(se, kq, e);  CHAIN4(sf, kq, fq);
                CHAIN4(sg, kq, gq); CHAIN4(sh, kq, hq);
            }
            int jb = t * 64 + g * 8;
            TOPK_INSERT(fmaxf(sa, 0.f), jb + 0);
            TOPK_INSERT(fmaxf(sb, 0.f), jb + 1);
            TOPK_INSERT(fmaxf(sc, 0.f), jb + 2);
            TOPK_INSERT(fmaxf(sd, 0.f), jb + 3);
            TOPK_INSERT(fmaxf(se, 0.f), jb + 4);
            TOPK_INSERT(fmaxf(sf, 0.f), jb + 5);
            TOPK_INSERT(fmaxf(sg, 0.f), jb + 6);
            TOPK_INSERT(fmaxf(sh, 0.f), jb + 7);
        }

        if (t + 1 < T / 64) {
            float4* dst = (float4*)Qs[(t + 1) & 1];
            dst[tid*4+0] = pf0;
            dst[tid*4+1] = pf1;
            dst[tid*4+2] = pf2;
            dst[tid*4+3] = pf3;
        }
        __syncthreads();
    }

    int* op = g_idx + (bT + i) * KNN;
    op[0]=j0; op[1]=j1; op[2]=j2; op[3]=j3; op[4]=j4;
    op[5]=j5; op[6]=j6; op[7]=j7; op[8]=j8;
}

// ---------------------------------------------------------------------------
// Kernel 3: gather v + 1x1 conv (576 -> 64) + bias (validated, 92us)
// ---------------------------------------------------------------------------
__global__ __launch_bounds__(128) void gather_conv_kernel(
    const float* __restrict__ conv_b,
    float* __restrict__ out)
{
    __shared__ float  Ws[C * C];
    __shared__ float4 Vs[4][16][33];

    const int b   = blockIdx.y;
    const int tid = threadIdx.x;
    const int w   = tid >> 5;
    const int l   = tid & 31;
    const int i   = blockIdx.x * 128 + tid;

    u64 accp[32];
    #pragma unroll
    for (int o2 = 0; o2 < 32; o2++) accp[o2] = 0ull;

    const int base = (b * T + i) * KNN;

    for (int kk = 0; kk < KNN; kk++) {
        __syncthreads();
        {
            const float4* wsrc = (const float4*)(g_wP + kk * C * C);
            float4* wdst = (float4*)Ws;
            #pragma unroll
            for (int r = 0; r < 8; r++)
                wdst[r * 128 + tid] = wsrc[r * 128 + tid];
        }

        int j = g_idx[base + kk];

        #pragma unroll
        for (int rp = 0; rp < 32; rp += 2) {
            int r  = rp + (l >> 4);
            int c4 = l & 15;
            int jr = __shfl_sync(0xffffffffu, j, r);
            float4 vv = ((const float4*)(g_vT + ((size_t)b * T + jr) * C))[c4];
            Vs[w][c4][r] = vv;
        }
        __syncthreads();

        #pragma unroll
        for (int c4 = 0; c4 < 16; c4++) {
            float4 xv = Vs[w][c4][l];
            float xs[4] = {xv.x, xv.y, xv.z, xv.w};
            #pragma unroll
            for (int e = 0; e < 4; e++) {
                u64 xd = pk2(xs[e], xs[e]);
                const ulonglong2* wr = (const ulonglong2*)(Ws + (c4 * 4 + e) * C);
                #pragma unroll
                for (int o4 = 0; o4 < 16; o4++) {
                    ulonglong2 wp = wr[o4];
                    accp[2*o4+0] = fma2(xd, wp.x, accp[2*o4+0]);
                    accp[2*o4+1] = fma2(xd, wp.y, accp[2*o4+1]);
                }
            }
        }
    }

    #pragma unroll
    for (int o2 = 0; o2 < 32; o2++) {
        float f0, f1;
        unpk(accp[o2], f0, f1);
        out[((size_t)(b * C + 2*o2 + 0)) * T + i] = f0 + __ldg(&conv_b[2*o2 + 0]);
        out[((size_t)(b * C + 2*o2 + 1)) * T + i] = f1 + __ldg(&conv_b[2*o2 + 1]);
    }
}

// ---------------------------------------------------------------------------
extern "C" void kernel_launch(void* const* d_in, const int* in_sizes, int n_in,
                              void* d_out, int out_size)
{
    const float* x      = (const float*)d_in[0];
    const float* Wq     = (const float*)d_in[1];
    const float* Wk     = (const float*)d_in[2];
    const float* Wv     = (const float*)d_in[3];
    const float* conv_w = (const float*)d_in[4];
    const float* conv_b = (const float*)d_in[5];
    float* out          = (float*)d_out;

    permute_w_kernel<<<(KNN * C * C + 255) / 256, 256>>>(conv_w);
    proj_kernel<<<dim3(T / 128, B), 128>>>(x, Wq, Wk, Wv);
    sim_topk_kernel<<<dim3(T / 256, B), 256>>>();
    gather_conv_kernel<<<dim3(T / 128, B), 128>>>(conv_b, out);
}

// round 13
// speedup vs baseline: 10.0875x; 1.1807x over previous
#include <cuda_runtime.h>
#include <stdint.h>
#include <math.h>

#define B    8
#define C    64
#define T    4096
#define KNN  9
#define NT   (T / 128)   // 32 tiles of 128 q-rows

typedef unsigned long long u64;
typedef unsigned int       u32;

// Scratch (allocation-free: __device__ globals)
__device__ float g_qT[B * T * C];      // normalized q fp32 [b][t][c]
__device__ float g_kT[B * T * C];      // normalized k fp32
__device__ float g_vT[B * T * C];      // v fp32
__device__ float g_wP[KNN * C * C];    // conv_w permuted [kk][cc][o]
__device__ int   g_idx[B * T * KNN];   // top-9 indices per (b,i)

// ---------------------------------------------------------------------------
__device__ __forceinline__ u32 smem_u32(const void* p) {
    u32 a;
    asm("{ .reg .u64 t; cvta.to.shared.u64 t, %1; cvt.u32.u64 %0, t; }"
        : "=r"(a) : "l"(p));
    return a;
}
__device__ __forceinline__ u64 pk2(float lo, float hi) {
    u64 r; asm("mov.b64 %0, {%1, %2};" : "=l"(r) : "f"(lo), "f"(hi)); return r;
}
__device__ __forceinline__ u64 fma2(u64 a, u64 b, u64 c) {
    u64 d; asm("fma.rn.f32x2 %0, %1, %2, %3;" : "=l"(d) : "l"(a), "l"(b), "l"(c));
    return d;
}
__device__ __forceinline__ void unpk(u64 v, float& lo, float& hi) {
    asm("mov.b64 {%0, %1}, %2;" : "=f"(lo), "=f"(hi) : "l"(v));
}
__device__ __forceinline__ void cpa16(u32 daddr, const void* gptr) {
    asm volatile("cp.async.cg.shared.global [%0], [%1], 16;"
                 :: "r"(daddr), "l"(gptr) : "memory");
}
#define CPA_COMMIT() asm volatile("cp.async.commit_group;" ::: "memory")
#define CPA_WAIT0()  asm volatile("cp.async.wait_group 0;" ::: "memory")

// ---------------------------------------------------------------------------
__global__ void permute_w_kernel(const float* __restrict__ conv_w) {
    int s = blockIdx.x * 256 + threadIdx.x;
    if (s < KNN * C * C) {
        int o  = s & 63;
        int cc = (s >> 6) & 63;
        int kk = s >> 12;
        g_wP[s] = conv_w[o * (C * KNN) + cc * KNN + kk];
    }
}

// ---------------------------------------------------------------------------
// Kernel 1: projections + L2 normalize (q,k); fp32 outputs.
// Numerics validated at rel_err 5.3e-7 (R3).
// ---------------------------------------------------------------------------
__global__ __launch_bounds__(128) void proj_kernel(
    const float* __restrict__ x,
    const float* __restrict__ Wq,
    const float* __restrict__ Wk,
    const float* __restrict__ Wv)
{
    __shared__ float Xs[C][128];
    __shared__ float Ws[C][C];

    const int b   = blockIdx.y;
    const int t0  = blockIdx.x * 128;
    const int tid = threadIdx.x;

    const float* xb = x + (size_t)b * C * T;
    for (int c = 0; c < C; c++)
        Xs[c][tid] = xb[c * T + t0 + tid];

    for (int m = 0; m < 3; m++) {
        const float* W = (m == 0) ? Wq : ((m == 1) ? Wk : Wv);
        float* dstbase = (m == 0) ? g_qT : ((m == 1) ? g_kT : g_vT);

        __syncthreads();
        for (int s = tid; s < C * C; s += 128) {
            int c = s >> 6, d = s & 63;
            Ws[c][d] = W[d * C + c];
        }
        __syncthreads();

        float acc[C];
        #pragma unroll
        for (int d = 0; d < C; d++) acc[d] = 0.f;

        for (int c = 0; c < C; c++) {
            float xv = Xs[c][tid];
            const float4* wr = (const float4*)Ws[c];
            #pragma unroll
            for (int d4 = 0; d4 < 16; d4++) {
                float4 w = wr[d4];
                acc[4*d4+0] = __fmaf_rn(w.x, xv, acc[4*d4+0]);
                acc[4*d4+1] = __fmaf_rn(w.y, xv, acc[4*d4+1]);
                acc[4*d4+2] = __fmaf_rn(w.z, xv, acc[4*d4+2]);
                acc[4*d4+3] = __fmaf_rn(w.w, xv, acc[4*d4+3]);
            }
        }

        if (m < 2) {
            float ss = 0.f;
            #pragma unroll
            for (int d = 0; d < C; d++)
                ss = __fadd_rn(ss, __fmul_rn(acc[d], acc[d]));
            float n = fmaxf(sqrtf(ss), 1e-12f);
            #pragma unroll
            for (int d = 0; d < C; d++)
                acc[d] = __fdiv_rn(acc[d], n);
        }

        float4* dst = (float4*)(dstbase + ((size_t)b * T + t0 + tid) * C);
        #pragma unroll
        for (int d4 = 0; d4 < 16; d4++)
            dst[d4] = make_float4(acc[4*d4+0], acc[4*d4+1], acc[4*d4+2], acc[4*d4+3]);
    }
}

// ---------------------------------------------------------------------------
// Kernel 2: exact fp32 sim + streaming top-9 (R3 structure, validated) with
// cp.async double-buffered q tiles: copy of tile t+1 overlaps compute of t.
// ---------------------------------------------------------------------------
#define CSWAP(va, ja, vb, jb)                                     \
    do { if ((vb) > (va)) {                                       \
        float _tv = (va); (va) = (vb); (vb) = _tv;                \
        int   _tj = (ja); (ja) = (jb); (jb) = _tj; } } while (0)

#define TOPK_INSERT(s, j)                                         \
    do { if ((s) > v8) {                                          \
        v8 = (s); j8 = (j);                                       \
        CSWAP(v7, j7, v8, j8);                                    \
        CSWAP(v6, j6, v7, j7);                                    \
        CSWAP(v5, j5, v6, j6);                                    \
        CSWAP(v4, j4, v5, j5);                                    \
        CSWAP(v3, j3, v4, j4);                                    \
        CSWAP(v2, j2, v3, j3);                                    \
        CSWAP(v1, j1, v2, j2);                                    \
        CSWAP(v0, j0, v1, j1); } } while (0)

__global__ __launch_bounds__(256) void sim_topk_kernel()
{
    extern __shared__ __align__(16) float Qd[];   // 2 x 128 x 64 floats (64 KB)

    const int    b   = blockIdx.y;
    const int    tid = threadIdx.x;
    const int    i   = blockIdx.x * 256 + tid;
    const size_t bT  = (size_t)b * T;

    float kr[C];
    {
        const float4* kp = (const float4*)(g_kT + (bT + i) * C);
        #pragma unroll
        for (int c4 = 0; c4 < 16; c4++) {
            float4 v = __ldg(kp + c4);
            kr[4*c4+0] = v.x; kr[4*c4+1] = v.y;
            kr[4*c4+2] = v.z; kr[4*c4+3] = v.w;
        }
    }

    float v0=-1.f,v1=-1.f,v2=-1.f,v3=-1.f,v4=-1.f,v5=-1.f,v6=-1.f,v7=-1.f,v8=-1.f;
    int   j0=0,j1=0,j2=0,j3=0,j4=0,j5=0,j6=0,j7=0,j8=0;

    const u32 qs0 = smem_u32(Qd);
    const u32 qs1 = qs0 + 128 * C * 4;
    const float4* gq = (const float4*)(g_qT + bT * C);   // f4-linear over tiles

    // prologue: stage tile 0 (8 x 16B per thread, coalesced)
    #pragma unroll
    for (int u = 0; u < 8; u++) {
        int l = u * 256 + tid;
        cpa16(qs0 + (u32)l * 16u, gq + l);
    }
    CPA_COMMIT();

    for (int t = 0; t < NT; t++) {
        CPA_WAIT0();
        __syncthreads();   // tile t visible to all; all warps done with buf (t+1)&1

        if (t + 1 < NT) {  // stage tile t+1 into the other buffer (overlapped)
            const float4* gn = gq + (t + 1) * 2048;
            u32 dst = ((t + 1) & 1) ? qs1 : qs0;
            #pragma unroll
            for (int u = 0; u < 8; u++) {
                int l = u * 256 + tid;
                cpa16(dst + (u32)l * 16u, gn + l);
            }
            CPA_COMMIT();
        }

        const float* Q = Qd + (t & 1) * (128 * C);

        #pragma unroll 2
        for (int jj = 0; jj < 128; jj += 4) {
            const float4* qa = (const float4*)(Q + (jj + 0) * C);
            const float4* qb = (const float4*)(Q + (jj + 1) * C);
            const float4* qc = (const float4*)(Q + (jj + 2) * C);
            const float4* qd = (const float4*)(Q + (jj + 3) * C);
            float sa = 0.f, sb = 0.f, sc = 0.f, sd = 0.f;
            #pragma unroll
            for (int c4 = 0; c4 < 16; c4++) {
                float4 a4 = qa[c4], b4 = qb[c4], c4v = qc[c4], d4 = qd[c4];
                // strictly sequential chain per candidate (reference dot order)
                sa = __fmaf_rn(kr[4*c4+0], a4.x, sa);
                sb = __fmaf_rn(kr[4*c4+0], b4.x, sb);
                sc = __fmaf_rn(kr[4*c4+0], c4v.x, sc);
                sd = __fmaf_rn(kr[4*c4+0], d4.x, sd);
                sa = __fmaf_rn(kr[4*c4+1], a4.y, sa);
                sb = __fmaf_rn(kr[4*c4+1], b4.y, sb);
                sc = __fmaf_rn(kr[4*c4+1], c4v.y, sc);
                sd = __fmaf_rn(kr[4*c4+1], d4.y, sd);
                sa = __fmaf_rn(kr[4*c4+2], a4.z, sa);
                sb = __fmaf_rn(kr[4*c4+2], b4.z, sb);
                sc = __fmaf_rn(kr[4*c4+2], c4v.z, sc);
                sd = __fmaf_rn(kr[4*c4+2], d4.z, sd);
                sa = __fmaf_rn(kr[4*c4+3], a4.w, sa);
                sb = __fmaf_rn(kr[4*c4+3], b4.w, sb);
                sc = __fmaf_rn(kr[4*c4+3], c4v.w, sc);
                sd = __fmaf_rn(kr[4*c4+3], d4.w, sd);
            }
            int jb = t * 128 + jj;
            TOPK_INSERT(fmaxf(sa, 0.f), jb + 0);
            TOPK_INSERT(fmaxf(sb, 0.f), jb + 1);
            TOPK_INSERT(fmaxf(sc, 0.f), jb + 2);
            TOPK_INSERT(fmaxf(sd, 0.f), jb + 3);
        }
    }

    int* op = g_idx + (bT + i) * KNN;
    op[0]=j0; op[1]=j1; op[2]=j2; op[3]=j3; op[4]=j4;
    op[5]=j5; op[6]=j6; op[7]=j7; op[8]=j8;
}

// ---------------------------------------------------------------------------
// Kernel 3: gather v + 1x1 conv (576 -> 64) + bias (validated, 92us)
// ---------------------------------------------------------------------------
__global__ __launch_bounds__(128) void gather_conv_kernel(
    const float* __restrict__ conv_b,
    float* __restrict__ out)
{
    __shared__ float  Ws[C * C];
    __shared__ float4 Vs[4][16][33];

    const int b   = blockIdx.y;
    const int tid = threadIdx.x;
    const int w   = tid >> 5;
    const int l   = tid & 31;
    const int i   = blockIdx.x * 128 + tid;

    u64 accp[32];
    #pragma unroll
    for (int o2 = 0; o2 < 32; o2++) accp[o2] = 0ull;

    const int base = (b * T + i) * KNN;

    for (int kk = 0; kk < KNN; kk++) {
        __syncthreads();
        {
            const float4* wsrc = (const float4*)(g_wP + kk * C * C);
            float4* wdst = (float4*)Ws;
            #pragma unroll
            for (int r = 0; r < 8; r++)
                wdst[r * 128 + tid] = wsrc[r * 128 + tid];
        }

        int j = g_idx[base + kk];

        #pragma unroll
        for (int rp = 0; rp < 32; rp += 2) {
            int r  = rp + (l >> 4);
            int c4 = l & 15;
            int jr = __shfl_sync(0xffffffffu, j, r);
            float4 vv = ((const float4*)(g_vT + ((size_t)b * T + jr) * C))[c4];
            Vs[w][c4][r] = vv;
        }
        __syncthreads();

        #pragma unroll
        for (int c4 = 0; c4 < 16; c4++) {
            float4 xv = Vs[w][c4][l];
            float xs[4] = {xv.x, xv.y, xv.z, xv.w};
            #pragma unroll
            for (int e = 0; e < 4; e++) {
                u64 xd = pk2(xs[e], xs[e]);
                const ulonglong2* wr = (const ulonglong2*)(Ws + (c4 * 4 + e) * C);
                #pragma unroll
                for (int o4 = 0; o4 < 16; o4++) {
                    ulonglong2 wp = wr[o4];
                    accp[2*o4+0] = fma2(xd, wp.x, accp[2*o4+0]);
                    accp[2*o4+1] = fma2(xd, wp.y, accp[2*o4+1]);
                }
            }
        }
    }

    #pragma unroll
    for (int o2 = 0; o2 < 32; o2++) {
        float f0, f1;
        unpk(accp[o2], f0, f1);
        out[((size_t)(b * C + 2*o2 + 0)) * T + i] = f0 + __ldg(&conv_b[2*o2 + 0]);
        out[((size_t)(b * C + 2*o2 + 1)) * T + i] = f1 + __ldg(&conv_b[2*o2 + 1]);
    }
}

// ---------------------------------------------------------------------------
extern "C" void kernel_launch(void* const* d_in, const int* in_sizes, int n_in,
                              void* d_out, int out_size)
{
    const float* x      = (const float*)d_in[0];
    const float* Wq     = (const float*)d_in[1];
    const float* Wk     = (const float*)d_in[2];
    const float* Wv     = (const float*)d_in[3];
    const float* conv_w = (const float*)d_in[4];
    const float* conv_b = (const float*)d_in[5];
    float* out          = (float*)d_out;

    cudaFuncSetAttribute(sim_topk_kernel,
                         cudaFuncAttributeMaxDynamicSharedMemorySize, 65536);

    permute_w_kernel<<<(KNN * C * C + 255) / 256, 256>>>(conv_w);
    proj_kernel<<<dim3(T / 128, B), 128>>>(x, Wq, Wk, Wv);
    sim_topk_kernel<<<dim3(T / 256, B), 256, 65536>>>();
    gather_conv_kernel<<<dim3(T / 128, B), 128>>>(conv_b, out);
}

// round 14
// speedup vs baseline: 10.2100x; 1.0121x over previous
#include <cuda_runtime.h>
#include <cuda_bf16.h>
#include <stdint.h>
#include <math.h>

#define B      8
#define C      64
#define T      4096
#define KNN    9
#define NTILES (T / 128)      // 32 j-tiles of 128
#define NLANE  12             // per-(thread,row) approx list depth
#define MMERGE 24             // merged per-row shortlist depth
#define ERRB   0.006f         // >= rigorous bf16 product bound 2^-8 = 0.0039

typedef unsigned long long u64;
typedef unsigned int       u32;

// Scratch (allocation-free: __device__ globals)
__device__ float g_qT[B * T * C];                         // normalized q fp32 [b][t][c]
__device__ float g_kT[B * T * C];                         // normalized k fp32
__device__ float g_vT[B * T * C];                         // v fp32
__device__ __align__(16) __nv_bfloat16 g_qB[B * T * C];   // bf16 copy of g_qT
__device__ __align__(16) __nv_bfloat16 g_kB[B * T * C];   // bf16 copy of g_kT
__device__ float g_wP[KNN * C * C];                       // conv_w permuted [kk][cc][o]
__device__ int   g_idx[B * T * KNN];                      // top-9 indices per (b,i)

// smem layout constants (bytes, within dynamic smem) -- sim kernel
#define A_OFF    0             // 128 rows x 144B = 18432
#define B_OFF    18432         // 128 rows x 144B = 18432   (main phase)
#define LIST_OFF 0             // [8 warps][32 lanes][2][12] u64 = 49152 (overlay)
#define MK_OFF   49152         // [8][16][24] u64 = 24576
#define ACUT_OFF 73728         // [8][16] float = 512
#define SMEM_SZ  74240
#define STG_STRIDE 68          // floats per staged row (rerank)

// gather kernel dynamic smem: Ws 16384B + Vs[256][17] float4 = 69632B
#define GW_OFF   0
#define GV_OFF   16384
#define GSMEM_SZ (16384 + 256 * 17 * 16)

// ---------------------------------------------------------------------------
// helpers
// ---------------------------------------------------------------------------
__device__ __forceinline__ u32 smem_u32(const void* p) {
    u32 a;
    asm("{ .reg .u64 t; cvta.to.shared.u64 t, %1; cvt.u32.u64 %0, t; }"
        : "=r"(a) : "l"(p));
    return a;
}
__device__ __forceinline__ void ldm4(u32* r, u32 addr) {
    asm volatile("ldmatrix.sync.aligned.m8n8.x4.shared.b16 {%0,%1,%2,%3}, [%4];"
                 : "=r"(r[0]), "=r"(r[1]), "=r"(r[2]), "=r"(r[3]) : "r"(addr));
}
__device__ __forceinline__ void mma16816(float* c, const u32* a, const u32* b) {
    asm volatile("mma.sync.aligned.m16n8k16.row.col.f32.bf16.bf16.f32 "
                 "{%0,%1,%2,%3}, {%4,%5,%6,%7}, {%8,%9}, {%0,%1,%2,%3};"
                 : "+f"(c[0]), "+f"(c[1]), "+f"(c[2]), "+f"(c[3])
                 : "r"(a[0]), "r"(a[1]), "r"(a[2]), "r"(a[3]),
                   "r"(b[0]), "r"(b[1]));
}

// ---------------------------------------------------------------------------
// Kernel 0: permute conv_w[o][cc*9+kk] -> wP[kk][cc][o]
// ---------------------------------------------------------------------------
__global__ void permute_w_kernel(const float* __restrict__ conv_w) {
    int s = blockIdx.x * 256 + threadIdx.x;
    if (s < KNN * C * C) {
        int o  = s & 63;
        int cc = (s >> 6) & 63;
        int kk = s >> 12;
        g_wP[s] = conv_w[o * (C * KNN) + cc * KNN + kk];
    }
}

// ---------------------------------------------------------------------------
// Kernel 1: q/k/v projections + L2 normalize (k,q); fp32 + bf16 outputs.
// (byte-identical to R8; validated at rel_err 5.3e-7)
// ---------------------------------------------------------------------------
__global__ __launch_bounds__(128) void proj_kernel(
    const float* __restrict__ x,
    const float* __restrict__ Wq,
    const float* __restrict__ Wk,
    const float* __restrict__ Wv)
{
    __shared__ float Xs[C][128];
    __shared__ float Ws[C][C];

    const int b   = blockIdx.y;
    const int t0  = blockIdx.x * 128;
    const int tid = threadIdx.x;

    const float* xb = x + (size_t)b * C * T;
    for (int c = 0; c < C; c++)
        Xs[c][tid] = xb[c * T + t0 + tid];

    for (int m = 0; m < 3; m++) {
        const float* W = (m == 0) ? Wq : ((m == 1) ? Wk : Wv);
        float* dstbase = (m == 0) ? g_qT : ((m == 1) ? g_kT : g_vT);

        __syncthreads();
        for (int s = tid; s < C * C; s += 128) {
            int c = s >> 6, d = s & 63;
            Ws[c][d] = W[d * C + c];
        }
        __syncthreads();

        float acc[C];
        #pragma unroll
        for (int d = 0; d < C; d++) acc[d] = 0.f;

        for (int c = 0; c < C; c++) {
            float xv = Xs[c][tid];
            const float4* wr = (const float4*)Ws[c];
            #pragma unroll
            for (int d4 = 0; d4 < 16; d4++) {
                float4 w = wr[d4];
                acc[4*d4+0] = __fmaf_rn(w.x, xv, acc[4*d4+0]);
                acc[4*d4+1] = __fmaf_rn(w.y, xv, acc[4*d4+1]);
                acc[4*d4+2] = __fmaf_rn(w.z, xv, acc[4*d4+2]);
                acc[4*d4+3] = __fmaf_rn(w.w, xv, acc[4*d4+3]);
            }
        }

        if (m < 2) {
            float ss = 0.f;
            #pragma unroll
            for (int d = 0; d < C; d++)
                ss = __fadd_rn(ss, __fmul_rn(acc[d], acc[d]));
            float n = fmaxf(sqrtf(ss), 1e-12f);
            #pragma unroll
            for (int d = 0; d < C; d++)
                acc[d] = __fdiv_rn(acc[d], n);
        }

        float4* dst = (float4*)(dstbase + ((size_t)b * T + t0 + tid) * C);
        #pragma unroll
        for (int d4 = 0; d4 < 16; d4++)
            dst[d4] = make_float4(acc[4*d4+0], acc[4*d4+1], acc[4*d4+2], acc[4*d4+3]);

        if (m < 2) {
            __nv_bfloat16* bb = (m == 0) ? g_qB : g_kB;
            __nv_bfloat162* bd = (__nv_bfloat162*)(bb + ((size_t)b * T + t0 + tid) * C);
            #pragma unroll
            for (int d2 = 0; d2 < 32; d2++)
                bd[d2] = __floats2bfloat162_rn(acc[2*d2], acc[2*d2+1]);
        }
    }
}

// ---------------------------------------------------------------------------
// Lex Top9: value desc, index asc on ties (== jax top_k). Any insert order.
// ---------------------------------------------------------------------------
struct Top9 {
    float v0,v1,v2,v3,v4,v5,v6,v7,v8;
    int   j0,j1,j2,j3,j4,j5,j6,j7,j8;
    __device__ __forceinline__ void init() {
        v0=v1=v2=v3=v4=v5=v6=v7=v8 = -1.f;
        j0=j1=j2=j3=j4=j5=j6=j7=j8 = 0x7FFFFFFF;
    }
    __device__ __forceinline__ void insert(float s, int j) {
        if ((s > v8) || (s == v8 && j < j8)) {
            v8 = s; j8 = j;
            #define _LSW(va,ja,vb,jb) if (((vb) > (va)) || ((vb) == (va) && (jb) < (ja))) { \
                float tv=(va); (va)=(vb); (vb)=tv; int tj=(ja); (ja)=(jb); (jb)=tj; }
            _LSW(v7,j7,v8,j8); _LSW(v6,j6,v7,j7); _LSW(v5,j5,v6,j6);
            _LSW(v4,j4,v5,j5); _LSW(v3,j3,v4,j4); _LSW(v2,j2,v3,j3);
            _LSW(v1,j1,v2,j2); _LSW(v0,j0,v1,j1);
            #undef _LSW
        }
    }
    __device__ __forceinline__ void store(int* op) {
        op[0]=j0; op[1]=j1; op[2]=j2; op[3]=j3; op[4]=j4;
        op[5]=j5; op[6]=j6; op[7]=j7; op[8]=j8;
    }
};

__device__ __forceinline__ float exact_dot_g(const float* __restrict__ kr,
                                             const float* __restrict__ qrow)
{
    const float4* q = (const float4*)qrow;
    float s = 0.f;
    #pragma unroll
    for (int c4 = 0; c4 < 16; c4++) {
        float4 qq = __ldg(&q[c4]);
        s = __fmaf_rn(kr[4*c4+0], qq.x, s);
        s = __fmaf_rn(kr[4*c4+1], qq.y, s);
        s = __fmaf_rn(kr[4*c4+2], qq.z, s);
        s = __fmaf_rn(kr[4*c4+3], qq.w, s);
    }
    return s;
}

#define PROC_SCORE(val, KL, MN, jj) do {                                      \
    float s_ = fmaxf((val), 0.f) + 1.0f;                                      \
    if (s_ > (MN)) {                                                          \
        u64 key_ = ((u64)__float_as_uint(s_) << 32) | (u32)(0xFFFFu - (u32)(jj)); \
        KL[11] = key_;                                                        \
        _Pragma("unroll")                                                     \
        for (int z_ = 10; z_ >= 0; z_--)                                      \
            if (KL[z_+1] > KL[z_]) { u64 t_ = KL[z_]; KL[z_] = KL[z_+1]; KL[z_+1] = t_; } \
        MN = __uint_as_float((u32)(KL[11] >> 32));                            \
    } } while (0)

// ---------------------------------------------------------------------------
// Kernel 2: bf16 mma.sync prefilter -> per-row top-24 shortlist ->
//           exact fp32 re-rank -> lex Top9 (+ sound margin check/fallback).
// (byte-identical to R8 -- the best-measured configuration)
// ---------------------------------------------------------------------------
__global__ __launch_bounds__(256) void sim_topk_mma_kernel()
{
    extern __shared__ __align__(16) char dynsmem[];

    const int b    = blockIdx.y;
    const int tid  = threadIdx.x;
    const int w    = tid >> 5;
    const int lane = tid & 31;
    const int i0   = blockIdx.x * 128;

    const u32 sb = smem_u32(dynsmem);

    {
        const uint4* src = (const uint4*)(g_kB + ((size_t)b * T + i0) * C);
        #pragma unroll
        for (int it = 0; it < 4; it++) {
            int idx = it * 256 + tid;
            int row = idx >> 3, ch = idx & 7;
            uint4 v = __ldg(src + row * 8 + ch);
            *(uint4*)(dynsmem + A_OFF + row * 144 + ch * 16) = v;
        }
    }
    __syncthreads();

    u32 afr[4][4];
    {
        u32 abase = sb + A_OFF + (w * 16 + (lane & 15)) * 144 + (lane >> 4) * 16;
        #pragma unroll
        for (int ks = 0; ks < 4; ks++) ldm4(afr[ks], abase + ks * 32);
    }

    u64 kl0[NLANE], kl1[NLANE];
    float mn0 = 0.f, mn1 = 0.f;
    #pragma unroll
    for (int m = 0; m < NLANE; m++) { kl0[m] = 0ull; kl1[m] = 0ull; }

    const int jrow  = (lane & 7) + ((lane >> 4) << 3);
    const int khalf = (lane >> 3) & 1;
    const int q0    = 2 * (lane & 3);

    for (int t = 0; t < NTILES; t++) {
        __syncthreads();
        {
            const uint4* src = (const uint4*)(g_qB + ((size_t)b * T + (size_t)t * 128) * C);
            #pragma unroll
            for (int it = 0; it < 4; it++) {
                int idx = it * 256 + tid;
                int row = idx >> 3, ch = idx & 7;
                uint4 v = __ldg(src + row * 8 + ch);
                *(uint4*)(dynsmem + B_OFF + row * 144 + ch * 16) = v;
            }
        }
        __syncthreads();

        #pragma unroll 2
        for (int chunk = 0; chunk < 8; chunk++) {
            u32 bbase = sb + B_OFF + (chunk * 16 + jrow) * 144 + khalf * 16;
            float a0[4] = {0.f, 0.f, 0.f, 0.f};
            float a1[4] = {0.f, 0.f, 0.f, 0.f};
            #pragma unroll
            for (int ks = 0; ks < 4; ks++) {
                u32 bb[4];
                ldm4(bb, bbase + ks * 32);
                mma16816(a0, afr[ks], bb + 0);
                mma16816(a1, afr[ks], bb + 2);
            }
            int jb = t * 128 + chunk * 16 + q0;
            PROC_SCORE(a0[0], kl0, mn0, jb + 0);
            PROC_SCORE(a0[1], kl0, mn0, jb + 1);
            PROC_SCORE(a0[2], kl1, mn1, jb + 0);
            PROC_SCORE(a0[3], kl1, mn1, jb + 1);
            PROC_SCORE(a1[0], kl0, mn0, jb + 8);
            PROC_SCORE(a1[1], kl0, mn0, jb + 9);
            PROC_SCORE(a1[2], kl1, mn1, jb + 8);
            PROC_SCORE(a1[3], kl1, mn1, jb + 9);
        }
    }

    __syncthreads();
    u64* LST = (u64*)(dynsmem + LIST_OFF);
    {
        u64* my = LST + (size_t)(w * 32 + lane) * (2 * NLANE);
        #pragma unroll
        for (int m = 0; m < NLANE; m++) { my[m] = kl0[m]; my[NLANE + m] = kl1[m]; }
    }
    __syncwarp();

    u64*   MK  = (u64*)(dynsmem + MK_OFF);
    float* ACT = (float*)(dynsmem + ACUT_OFF);
    if ((lane & 1) == 0) {
        int r    = lane >> 2;
        int half = (lane >> 1) & 1;
        int rrow = r + half * 8;
        u64* mk  = MK + (size_t)(w * 16 + rrow) * MMERGE;
        #pragma unroll
        for (int m = 0; m < MMERGE; m++) mk[m] = 0ull;
        float acut = 0.f;
        for (int src = 0; src < 4; src++) {
            const u64* L = LST + (size_t)(w * 32 + r * 4 + src) * (2 * NLANE) + half * NLANE;
            acut = fmaxf(acut, __uint_as_float((u32)(L[NLANE - 1] >> 32)));
            for (int e = 0; e < NLANE; e++) {
                u64 key = L[e];
                if (!(key >> 32)) break;
                if (key <= mk[MMERGE - 1]) continue;
                mk[MMERGE - 1] = key;
                for (int z = MMERGE - 2; z >= 0; z--) {
                    if (mk[z + 1] > mk[z]) { u64 tk = mk[z]; mk[z] = mk[z + 1]; mk[z + 1] = tk; }
                    else break;
                }
            }
        }
        acut = fmaxf(acut, __uint_as_float((u32)(mk[MMERGE - 1] >> 32)));
        ACT[w * 16 + rrow] = acut;
    }
    __syncwarp();

    float kr[C];
    if (lane < 16) {
        const float4* kp4 = (const float4*)(g_kT + ((size_t)b * T + i0 + w * 16 + lane) * C);
        #pragma unroll
        for (int c4 = 0; c4 < 16; c4++) {
            float4 k4 = __ldg(&kp4[c4]);
            kr[4*c4+0] = k4.x; kr[4*c4+1] = k4.y;
            kr[4*c4+2] = k4.z; kr[4*c4+3] = k4.w;
        }
    }

    Top9 t9;
    t9.init();
    float* stg = (float*)(dynsmem + (size_t)w * 6144);

    for (int m = 0; m < MMERGE; m++) {
        __syncwarp();
        #pragma unroll
        for (int it = 0; it < 8; it++) {
            int idx = it * 32 + lane;
            int r = idx >> 4, c4 = idx & 15;
            u64 key = MK[(size_t)(w * 16 + r) * MMERGE + m];
            int jc = (key >> 32) ? (int)(0xFFFFu - (u32)(key & 0xFFFFu)) : 0;
            float4 qv = __ldg((const float4*)(g_qT + ((size_t)b * T + jc) * C) + c4);
            *(float4*)(stg + r * STG_STRIDE + c4 * 4) = qv;
        }
        __syncwarp();
        if (lane < 16) {
            u64 key = MK[(size_t)(w * 16 + lane) * MMERGE + m];
            if (key >> 32) {
                int jc = (int)(0xFFFFu - (u32)(key & 0xFFFFu));
                const float4* qs = (const float4*)(stg + lane * STG_STRIDE);
                float s = 0.f;
                #pragma unroll
                for (int c4 = 0; c4 < 16; c4++) {
                    float4 q = qs[c4];
                    s = __fmaf_rn(kr[4*c4+0], q.x, s);
                    s = __fmaf_rn(kr[4*c4+1], q.y, s);
                    s = __fmaf_rn(kr[4*c4+2], q.z, s);
                    s = __fmaf_rn(kr[4*c4+3], q.w, s);
                }
                t9.insert(fmaxf(s, 0.f), jc);
            }
        }
    }

    if (lane < 16) {
        float acut = ACT[w * 16 + lane];
        if (acut - 1.0f + ERRB >= t9.v8) {
            t9.init();
            const float* qb = g_qT + (size_t)b * T * C;
            for (int j = 0; j < T; j++) {
                float s = fmaxf(exact_dot_g(kr, qb + (size_t)j * C), 0.f);
                t9.insert(s, j);
            }
        }
        t9.store(g_idx + ((size_t)b * T + i0 + w * 16 + lane) * KNN);
    }
}

// ---------------------------------------------------------------------------
// Kernel 3 (REWORKED): gather v + 1x1 conv (576 -> 64) + bias.
// 128 CTAs x 512 threads (single wave, 4 warps/SMSP). 256 columns per CTA,
// 2 threads per column (32 outputs each). Plain scalar FFMA; conflict-free
// Vs[col][c4] staging; coalesced output.
// ---------------------------------------------------------------------------
__global__ __launch_bounds__(512) void gather_conv_kernel(
    const float* __restrict__ conv_b,
    float* __restrict__ out)
{
    extern __shared__ __align__(16) char gsmem[];
    float*  Ws = (float*)(gsmem + GW_OFF);           // [cc][o] 64x64
    float4* Vs = (float4*)(gsmem + GV_OFF);          // [col][17], col 0..255

    const int b    = blockIdx.y;
    const int tid  = threadIdx.x;
    const int col  = tid & 255;
    const int half = tid >> 8;           // 0 or 1 (uniform per warp)
    const int i0   = blockIdx.x * 256;
    const int i    = i0 + col;
    const size_t bT = (size_t)b * T;

    float acc[32];
    #pragma unroll
    for (int o = 0; o < 32; o++) acc[o] = 0.f;

    for (int kk = 0; kk < KNN; kk++) {
        __syncthreads();
        // stage Ws: 1024 float4, 512 threads -> 2 each (coalesced)
        {
            const float4* wsrc = (const float4*)(g_wP + kk * C * C);
            float4* wdst = (float4*)Ws;
            wdst[tid]       = __ldg(wsrc + tid);
            wdst[512 + tid] = __ldg(wsrc + 512 + tid);
        }
        // stage Vs: 256 cols x 16 float4 = 4096, 512 threads -> 8 each
        #pragma unroll
        for (int u = 0; u < 8; u++) {
            int idx = u * 512 + tid;
            int cs  = idx >> 4;
            int c4  = idx & 15;
            int j   = __ldg(&g_idx[(bT + i0 + cs) * KNN + kk]);
            Vs[cs * 17 + c4] = __ldg((const float4*)(g_vT + (bT + j) * C) + c4);
        }
        __syncthreads();

        const float4* vcol = Vs + col * 17;
        #pragma unroll
        for (int c4 = 0; c4 < 16; c4++) {
            float4 xv = vcol[c4];
            float xs[4] = {xv.x, xv.y, xv.z, xv.w};
            #pragma unroll
            for (int e = 0; e < 4; e++) {
                float xe = xs[e];
                const float4* wr = (const float4*)(Ws + (c4 * 4 + e) * C + half * 32);
                #pragma unroll
                for (int o4 = 0; o4 < 8; o4++) {
                    float4 w = wr[o4];
                    acc[4*o4+0] = __fmaf_rn(xe, w.x, acc[4*o4+0]);
                    acc[4*o4+1] = __fmaf_rn(xe, w.y, acc[4*o4+1]);
                    acc[4*o4+2] = __fmaf_rn(xe, w.z, acc[4*o4+2]);
                    acc[4*o4+3] = __fmaf_rn(xe, w.w, acc[4*o4+3]);
                }
            }
        }
    }

    // out[b][half*32+o][i] (+bias); warp spans 32 consecutive i -> coalesced
    #pragma unroll
    for (int o = 0; o < 32; o++) {
        int oc = half * 32 + o;
        out[((size_t)(b * C + oc)) * T + i] = acc[o] + __ldg(&conv_b[oc]);
    }
}

// ---------------------------------------------------------------------------
extern "C" void kernel_launch(void* const* d_in, const int* in_sizes, int n_in,
                              void* d_out, int out_size)
{
    const float* x      = (const float*)d_in[0];
    const float* Wq     = (const float*)d_in[1];
    const float* Wk     = (const float*)d_in[2];
    const float* Wv     = (const float*)d_in[3];
    const float* conv_w = (const float*)d_in[4];
    const float* conv_b = (const float*)d_in[5];
    float* out          = (float*)d_out;

    cudaFuncSetAttribute(sim_topk_mma_kernel,
                         cudaFuncAttributeMaxDynamicSharedMemorySize, SMEM_SZ);
    cudaFuncSetAttribute(gather_conv_kernel,
                         cudaFuncAttributeMaxDynamicSharedMemorySize, GSMEM_SZ);

    permute_w_kernel<<<(KNN * C * C + 255) / 256, 256>>>(conv_w);
    proj_kernel<<<dim3(T / 128, B), 128>>>(x, Wq, Wk, Wv);
    sim_topk_mma_kernel<<<dim3(T / 128, B), 256, SMEM_SZ>>>();
    gather_conv_kernel<<<dim3(T / 256, B), 512, GSMEM_SZ>>>(conv_b, out);
}